// round 2
// baseline (speedup 1.0000x reference)
#include <cuda_runtime.h>

#define D 128
#define H 64
#define NMAX 100032
#define EMAX 1600000
#define FULL 0xffffffffu

// ---------------- scratch (static device globals; no allocations) -------------
__device__ float g_weights[NMAX];                 // per-node sigmoid gate
__device__ int   g_deg[NMAX];
__device__ int   g_rowoff[NMAX + 1];
__device__ int   g_cursor[NMAX];
__device__ int   g_csrcol[EMAX];
__device__ float g_readout[(size_t)NMAX * D];     // segment sums
__device__ float g_hidden[(size_t)NMAX * H];      // relu(readout@W1+b1)
__device__ int   g_partials[256];
__device__ int   g_is64;                          // 1 = edge_index is int64, 0 = int32

// ---------------- dtype detection (1 warp) -------------------------------------
__global__ void k_detect(const void* __restrict__ ei, int E, int N) {
    const long long* e64 = (const long long*)ei;
    int lane = threadIdx.x;
    int ok = 1;
    if (lane < E) {
        long long v = e64[lane];
        ok = (v >= 0 && v < (long long)N) ? 1 : 0;
    }
    unsigned m = __ballot_sync(FULL, ok);
    if (lane == 0) g_is64 = (m == FULL) ? 1 : 0;
}

__device__ __forceinline__ int edge_at(const void* ei, size_t idx, int is64, int N) {
    long long v = is64 ? ((const long long*)ei)[idx] : (long long)((const int*)ei)[idx];
    if (v < 0) v = 0;
    if (v >= N) v = N - 1;
    return (int)v;
}

// ---------------- zero degree counts ------------------------------------------
__global__ void k_zero(int N) {
    int i = blockIdx.x * blockDim.x + threadIdx.x;
    if (i < N) g_deg[i] = 0;
}

// ---------------- gate: weights = sigmoid(tanh(x@Wsim+bsim)@wvec + bvec) ------
__global__ void k_gate(const float4* __restrict__ x4, const float* __restrict__ Wsim,
                       const float* __restrict__ bsim, const float* __restrict__ wvec,
                       const float* __restrict__ bvec, int N) {
    __shared__ float sW[D * H];
    __shared__ float sb[H], sv[H];
    int tid = threadIdx.x;
    for (int i = tid; i < D * H; i += blockDim.x) sW[i] = Wsim[i];
    if (tid < H) { sb[tid] = bsim[tid]; sv[tid] = wvec[tid]; }
    __syncthreads();
    float bv = bvec[0];
    int lane = tid & 31, wp = tid >> 5;
    int gw = blockIdx.x * (blockDim.x >> 5) + wp;
    int nw = gridDim.x * (blockDim.x >> 5);
    int ngroups = (N + 3) >> 2;
    for (int g = gw; g < ngroups; g += nw) {
        int n0 = g * 4;
        float4 xv[4]; float a0[4], a1[4];
        #pragma unroll
        for (int t = 0; t < 4; t++) {
            int n = n0 + t;
            xv[t] = (n < N) ? x4[(size_t)n * 32 + lane] : make_float4(0.f, 0.f, 0.f, 0.f);
            a0[t] = sb[lane]; a1[t] = sb[lane + 32];
        }
        #pragma unroll 8
        for (int kk = 0; kk < 32; kk++) {
            float w00 = sW[(4 * kk + 0) * H + lane], w01 = sW[(4 * kk + 0) * H + lane + 32];
            float w10 = sW[(4 * kk + 1) * H + lane], w11 = sW[(4 * kk + 1) * H + lane + 32];
            float w20 = sW[(4 * kk + 2) * H + lane], w21 = sW[(4 * kk + 2) * H + lane + 32];
            float w30 = sW[(4 * kk + 3) * H + lane], w31 = sW[(4 * kk + 3) * H + lane + 32];
            #pragma unroll
            for (int t = 0; t < 4; t++) {
                float bx = __shfl_sync(FULL, xv[t].x, kk);
                float by = __shfl_sync(FULL, xv[t].y, kk);
                float bz = __shfl_sync(FULL, xv[t].z, kk);
                float bw = __shfl_sync(FULL, xv[t].w, kk);
                a0[t] += bx * w00 + by * w10 + bz * w20 + bw * w30;
                a1[t] += bx * w01 + by * w11 + bz * w21 + bw * w31;
            }
        }
        #pragma unroll
        for (int t = 0; t < 4; t++) {
            float h0 = tanhf(a0[t]), h1 = tanhf(a1[t]);
            float s = h0 * sv[lane] + h1 * sv[lane + 32];
            #pragma unroll
            for (int o = 16; o > 0; o >>= 1) s += __shfl_xor_sync(FULL, s, o);
            if (lane == 0 && n0 + t < N)
                g_weights[n0 + t] = 1.f / (1.f + __expf(-(s + bv)));
        }
    }
}

// ---------------- CSR build ----------------------------------------------------
__global__ void k_hist(const void* __restrict__ ei, int E, int N) {
    int is64 = g_is64;
    int i = blockIdx.x * blockDim.x + threadIdx.x;
    int stride = gridDim.x * blockDim.x;
    for (; i < E; i += stride) atomicAdd(&g_deg[edge_at(ei, i, is64, N)], 1);
}

__global__ void k_scan1(int N) {   // per-1024-chunk sums
    int i = blockIdx.x * 1024 + threadIdx.x;
    int v = (i < N) ? g_deg[i] : 0;
    #pragma unroll
    for (int o = 16; o > 0; o >>= 1) v += __shfl_xor_sync(FULL, v, o);
    __shared__ int ws[32];
    int lane = threadIdx.x & 31, w = threadIdx.x >> 5;
    if (lane == 0) ws[w] = v;
    __syncthreads();
    if (w == 0) {
        int s = ws[lane];
        #pragma unroll
        for (int o = 16; o > 0; o >>= 1) s += __shfl_xor_sync(FULL, s, o);
        if (lane == 0) g_partials[blockIdx.x] = s;
    }
}

__global__ void k_scan2(int nblk, int N, int E) {  // exclusive scan of chunk sums
    __shared__ int s[128];
    int tid = threadIdx.x;
    int v = (tid < nblk) ? g_partials[tid] : 0;
    s[tid] = v;
    __syncthreads();
    for (int o = 1; o < 128; o <<= 1) {
        int t = 0;
        if (tid >= o) t = s[tid - o];
        __syncthreads();
        s[tid] += t;
        __syncthreads();
    }
    if (tid < nblk) g_partials[tid] = s[tid] - v;
    if (tid == 0) g_rowoff[N] = E;
}

__global__ void k_scan3(int N) {   // within-chunk exclusive scan + base
    int i = blockIdx.x * 1024 + threadIdx.x;
    int lane = threadIdx.x & 31, w = threadIdx.x >> 5;
    int v = (i < N) ? g_deg[i] : 0;
    int s = v;
    #pragma unroll
    for (int o = 1; o < 32; o <<= 1) {
        int t = __shfl_up_sync(FULL, s, o);
        if (lane >= o) s += t;
    }
    __shared__ int ws[32];
    if (lane == 31) ws[w] = s;
    __syncthreads();
    if (w == 0) {
        int t2 = ws[lane];
        #pragma unroll
        for (int o = 1; o < 32; o <<= 1) {
            int u = __shfl_up_sync(FULL, t2, o);
            if (lane >= o) t2 += u;
        }
        ws[lane] = t2;
    }
    __syncthreads();
    int excl = s - v + ((w > 0) ? ws[w - 1] : 0) + g_partials[blockIdx.x];
    if (i < N) { g_rowoff[i] = excl; g_cursor[i] = excl; }
}

__global__ void k_fill(const void* __restrict__ ei, int E, int N) {
    int is64 = g_is64;
    int i = blockIdx.x * blockDim.x + threadIdx.x;
    int stride = gridDim.x * blockDim.x;
    for (; i < E; i += stride) {
        int r = edge_at(ei, i, is64, N);
        int c = edge_at(ei, (size_t)E + i, is64, N);
        int pos = atomicAdd(&g_cursor[r], 1);
        if (pos >= 0 && pos < EMAX) g_csrcol[pos] = c;
    }
}

// ---------------- gather-side segment sum: readout[n] = sum x[col]*w[col] ------
__global__ void k_gather(const float4* __restrict__ x4, int N) {
    int warp = (blockIdx.x * blockDim.x + threadIdx.x) >> 5;
    int lane = threadIdx.x & 31;
    if (warp >= N) return;
    int s = g_rowoff[warp], e = g_rowoff[warp + 1];
    float4 acc = make_float4(0.f, 0.f, 0.f, 0.f);
    int p = s;
    for (; p + 4 <= e; p += 4) {
        int c0 = g_csrcol[p], c1 = g_csrcol[p + 1], c2 = g_csrcol[p + 2], c3 = g_csrcol[p + 3];
        float w0 = g_weights[c0], w1 = g_weights[c1], w2 = g_weights[c2], w3 = g_weights[c3];
        float4 v0 = x4[(size_t)c0 * 32 + lane];
        float4 v1 = x4[(size_t)c1 * 32 + lane];
        float4 v2 = x4[(size_t)c2 * 32 + lane];
        float4 v3 = x4[(size_t)c3 * 32 + lane];
        acc.x += v0.x * w0 + v1.x * w1 + v2.x * w2 + v3.x * w3;
        acc.y += v0.y * w0 + v1.y * w1 + v2.y * w2 + v3.y * w3;
        acc.z += v0.z * w0 + v1.z * w1 + v2.z * w2 + v3.z * w3;
        acc.w += v0.w * w0 + v1.w * w1 + v2.w * w2 + v3.w * w3;
    }
    for (; p < e; p++) {
        int c = g_csrcol[p];
        float w = g_weights[c];
        float4 v = x4[(size_t)c * 32 + lane];
        acc.x += v.x * w; acc.y += v.y * w; acc.z += v.z * w; acc.w += v.w * w;
    }
    reinterpret_cast<float4*>(g_readout)[(size_t)warp * 32 + lane] = acc;
}

// ---------------- MLP layer 1: hidden = relu(readout@W1 + b1) ------------------
__global__ void k_mlp1(const float* __restrict__ W1, const float* __restrict__ b1, int N) {
    __shared__ float sW[D * H];
    __shared__ float sb[H];
    int tid = threadIdx.x;
    for (int i = tid; i < D * H; i += blockDim.x) sW[i] = W1[i];
    if (tid < H) sb[tid] = b1[tid];
    __syncthreads();
    const float4* r4 = reinterpret_cast<const float4*>(g_readout);
    int lane = tid & 31, wp = tid >> 5;
    int gw = blockIdx.x * (blockDim.x >> 5) + wp;
    int nw = gridDim.x * (blockDim.x >> 5);
    int ngroups = (N + 3) >> 2;
    for (int g = gw; g < ngroups; g += nw) {
        int n0 = g * 4;
        float4 xv[4]; float a0[4], a1[4];
        #pragma unroll
        for (int t = 0; t < 4; t++) {
            int n = n0 + t;
            xv[t] = (n < N) ? r4[(size_t)n * 32 + lane] : make_float4(0.f, 0.f, 0.f, 0.f);
            a0[t] = sb[lane]; a1[t] = sb[lane + 32];
        }
        #pragma unroll 8
        for (int kk = 0; kk < 32; kk++) {
            float w00 = sW[(4 * kk + 0) * H + lane], w01 = sW[(4 * kk + 0) * H + lane + 32];
            float w10 = sW[(4 * kk + 1) * H + lane], w11 = sW[(4 * kk + 1) * H + lane + 32];
            float w20 = sW[(4 * kk + 2) * H + lane], w21 = sW[(4 * kk + 2) * H + lane + 32];
            float w30 = sW[(4 * kk + 3) * H + lane], w31 = sW[(4 * kk + 3) * H + lane + 32];
            #pragma unroll
            for (int t = 0; t < 4; t++) {
                float bx = __shfl_sync(FULL, xv[t].x, kk);
                float by = __shfl_sync(FULL, xv[t].y, kk);
                float bz = __shfl_sync(FULL, xv[t].z, kk);
                float bw = __shfl_sync(FULL, xv[t].w, kk);
                a0[t] += bx * w00 + by * w10 + bz * w20 + bw * w30;
                a1[t] += bx * w01 + by * w11 + bz * w21 + bw * w31;
            }
        }
        #pragma unroll
        for (int t = 0; t < 4; t++) {
            int n = n0 + t;
            if (n < N) {
                g_hidden[(size_t)n * H + lane]      = fmaxf(a0[t], 0.f);
                g_hidden[(size_t)n * H + lane + 32] = fmaxf(a1[t], 0.f);
            }
        }
    }
}

// ---------------- MLP layer 2 + residual: out = x + hidden@W2 + b2 -------------
__global__ void k_mlp2(const float4* __restrict__ x4, const float* __restrict__ W2,
                       const float* __restrict__ b2, float4* __restrict__ out4, int N) {
    __shared__ float4 sW4[H * 32];     // W2 [64][128] as float4 rows
    __shared__ float4 sb2[32];
    int tid = threadIdx.x;
    float* sWf = reinterpret_cast<float*>(sW4);
    for (int i = tid; i < H * D; i += blockDim.x) sWf[i] = W2[i];
    if (tid < 32) sb2[tid] = reinterpret_cast<const float4*>(b2)[tid];
    __syncthreads();
    int lane = tid & 31, wp = tid >> 5;
    int gw = blockIdx.x * (blockDim.x >> 5) + wp;
    int nw = gridDim.x * (blockDim.x >> 5);
    int ngroups = (N + 3) >> 2;
    for (int g = gw; g < ngroups; g += nw) {
        int n0 = g * 4;
        float t0[4], t1[4]; float4 p[4];
        #pragma unroll
        for (int t = 0; t < 4; t++) {
            int n = n0 + t;
            if (n < N) {
                t0[t] = g_hidden[(size_t)n * H + lane];
                t1[t] = g_hidden[(size_t)n * H + lane + 32];
            } else { t0[t] = 0.f; t1[t] = 0.f; }
            p[t] = sb2[lane];
        }
        #pragma unroll 8
        for (int jj = 0; jj < 32; jj++) {
            float4 w0 = sW4[jj * 32 + lane];
            float4 w1 = sW4[(jj + 32) * 32 + lane];
            #pragma unroll
            for (int t = 0; t < 4; t++) {
                float u0 = __shfl_sync(FULL, t0[t], jj);
                float u1 = __shfl_sync(FULL, t1[t], jj);
                p[t].x += u0 * w0.x + u1 * w1.x;
                p[t].y += u0 * w0.y + u1 * w1.y;
                p[t].z += u0 * w0.z + u1 * w1.z;
                p[t].w += u0 * w0.w + u1 * w1.w;
            }
        }
        #pragma unroll
        for (int t = 0; t < 4; t++) {
            int n = n0 + t;
            if (n < N) {
                float4 xv = x4[(size_t)n * 32 + lane];
                out4[(size_t)n * 32 + lane] =
                    make_float4(xv.x + p[t].x, xv.y + p[t].y, xv.z + p[t].z, xv.w + p[t].w);
            }
        }
    }
}

// ---------------- launch -------------------------------------------------------
extern "C" void kernel_launch(void* const* d_in, const int* in_sizes, int n_in,
                              void* d_out, int out_size) {
    const float* x    = (const float*)d_in[0];
    const void*  ei   = d_in[1];
    const float* Wsim = (const float*)d_in[2];
    const float* bsim = (const float*)d_in[3];
    const float* wvec = (const float*)d_in[4];
    const float* bvec = (const float*)d_in[5];
    const float* W1   = (const float*)d_in[6];
    const float* b1   = (const float*)d_in[7];
    const float* W2   = (const float*)d_in[8];
    const float* b2   = (const float*)d_in[9];
    float* out = (float*)d_out;

    int N = in_sizes[0] / D;
    int E = in_sizes[1] / 2;
    int nblk = (N + 1023) / 1024;

    k_detect<<<1, 32>>>(ei, E, N);
    k_zero<<<(N + 255) / 256, 256>>>(N);
    k_gate<<<592, 256>>>((const float4*)x, Wsim, bsim, wvec, bvec, N);
    k_hist<<<2048, 256>>>(ei, E, N);
    k_scan1<<<nblk, 1024>>>(N);
    k_scan2<<<1, 128>>>(nblk, N, E);
    k_scan3<<<nblk, 1024>>>(N);
    k_fill<<<2048, 256>>>(ei, E, N);
    k_gather<<<(N + 7) / 8, 256>>>((const float4*)x, N);
    k_mlp1<<<592, 256>>>(W1, b1, N);
    k_mlp2<<<592, 256>>>((const float4*)x, W2, b2, (float4*)out, N);
}